// round 6
// baseline (speedup 1.0000x reference)
#include <cuda_runtime.h>
#include <cuda_bf16.h>
#include <cuda_fp8.h>
#include <cstdint>

#define B_      16
#define N_SP    2048
#define N_TM    64
#define M_OUT   2112
#define M_PAD   2176
#define KD      64
#define TILE    128
#define NTILES  17
#define NPAIRS  153      // 17*18/2 upper-triangular tile pairs

// Scratch: hi (bf16), plus scaled e4m3 splits for the cross terms.
// h8 = e4m3(hi/8), l8 = e4m3((x-hi)*8); product of mixed pair is unscaled.
__device__ __nv_bfloat16 g_hi[B_ * M_PAD * KD];
__device__ uint8_t       g_h8[B_ * M_PAD * KD];
__device__ uint8_t       g_l8[B_ * M_PAD * KD];

// ---------------------------------------------------------------------------
// Pass 1: fp32 -> (hi bf16, h8 e4m3, l8 e4m3), concat + zero-pad rows.
// ---------------------------------------------------------------------------
__global__ void convert_split_kernel(const float4* __restrict__ sp,
                                     const float4* __restrict__ tp) {
    const int TOT = B_ * M_PAD * (KD / 4);
    int idx = blockIdx.x * blockDim.x + threadIdx.x;
    if (idx >= TOT) return;
    int kq  = idx & 15;
    int row = (idx >> 4) % M_PAD;
    int b   = idx / (M_PAD * 16);

    float4 x = make_float4(0.f, 0.f, 0.f, 0.f);
    if (row < N_SP)
        x = sp[((long)b * N_SP + row) * 16 + kq];
    else if (row < M_OUT)
        x = tp[((long)b * N_TM + (row - N_SP)) * 16 + kq];

    float xf[4] = {x.x, x.y, x.z, x.w};
    union { __nv_bfloat16 h[4]; uint2 u; } uh;
    uint32_t h8p = 0, l8p = 0;
#pragma unroll
    for (int i = 0; i < 4; i++) {
        __nv_bfloat16 h = __float2bfloat16(xf[i]);
        float hf = __bfloat162float(h);
        float lo = xf[i] - hf;
        uh.h[i] = h;
        uint32_t h8 = __nv_cvt_float_to_fp8(hf * 0.125f, __NV_SATFINITE, __NV_E4M3);
        uint32_t l8 = __nv_cvt_float_to_fp8(lo * 8.0f,   __NV_SATFINITE, __NV_E4M3);
        h8p |= (h8 & 0xFFu) << (i * 8);
        l8p |= (l8 & 0xFFu) << (i * 8);
    }
    *reinterpret_cast<uint2*>(&g_hi[(long)idx * 4]) = uh.u;
    reinterpret_cast<uint32_t*>(g_h8)[idx] = h8p;
    reinterpret_cast<uint32_t*>(g_l8)[idx] = l8p;
}

// ---------------------------------------------------------------------------
// PTX helpers
// ---------------------------------------------------------------------------
__device__ __forceinline__ uint32_t smem_u32(const void* p) {
    uint32_t a;
    asm("{ .reg .u64 t; cvta.to.shared.u64 t, %1; cvt.u32.u64 %0, t; }"
        : "=r"(a) : "l"(p));
    return a;
}

__device__ __forceinline__ void ldsm_x4(uint32_t* r, uint32_t addr) {
    asm volatile("ldmatrix.sync.aligned.m8n8.x4.shared.b16 {%0,%1,%2,%3}, [%4];"
                 : "=r"(r[0]), "=r"(r[1]), "=r"(r[2]), "=r"(r[3]) : "r"(addr));
}

__device__ __forceinline__ void mma16816(float* c, const uint32_t* a,
                                         uint32_t b0, uint32_t b1) {
    asm volatile(
        "mma.sync.aligned.m16n8k16.row.col.f32.bf16.bf16.f32 "
        "{%0,%1,%2,%3}, {%4,%5,%6,%7}, {%8,%9}, {%0,%1,%2,%3};"
        : "+f"(c[0]), "+f"(c[1]), "+f"(c[2]), "+f"(c[3])
        : "r"(a[0]), "r"(a[1]), "r"(a[2]), "r"(a[3]), "r"(b0), "r"(b1));
}

__device__ __forceinline__ void mma16832_e4m3(float* c, const uint32_t* a,
                                              uint32_t b0, uint32_t b1) {
    asm volatile(
        "mma.sync.aligned.m16n8k32.row.col.f32.e4m3.e4m3.f32 "
        "{%0,%1,%2,%3}, {%4,%5,%6,%7}, {%8,%9}, {%0,%1,%2,%3};"
        : "+f"(c[0]), "+f"(c[1]), "+f"(c[2]), "+f"(c[3])
        : "r"(a[0]), "r"(a[1]), "r"(a[2]), "r"(a[3]), "r"(b0), "r"(b1));
}

__device__ __forceinline__ float tanh_relu(float x) {
    x = fmaxf(x, 0.0f);
    float y;
    asm("tanh.approx.f32 %0, %1;" : "=f"(y) : "f"(x));
    return y;
}

// ---------------------------------------------------------------------------
// Pass 2: one CTA (256 thr, 8 warps of 64x32) per upper-triangular tile pair.
// Mainloop: hh in bf16 (4 k16) + cross terms in e4m3 (2 k32).
// ---------------------------------------------------------------------------
#define ROWB       144                   // bf16 operand pitch (bytes)
#define ROWB8      80                    // fp8 operand pitch (bytes)
#define HI_TILE_B  (128 * ROWB)          // 18432
#define F8_TILE_B  (128 * ROWB8)         // 10240
// Layout: A_HI, B_HI, A_H8, A_L8, B_H8, B_L8
#define OFF_A_HI   0
#define OFF_B_HI   (HI_TILE_B)
#define OFF_A_H8   (2 * HI_TILE_B)
#define OFF_A_L8   (2 * HI_TILE_B + F8_TILE_B)
#define OFF_B_H8   (2 * HI_TILE_B + 2 * F8_TILE_B)
#define OFF_B_L8   (2 * HI_TILE_B + 3 * F8_TILE_B)
#define SMEM_BYTES (2 * HI_TILE_B + 4 * F8_TILE_B)   // 77824
#define TPITCH     132                   // epilogue transpose pitch (floats)

__global__ void __launch_bounds__(256, 2)
gram_kernel(float* __restrict__ out) {
    extern __shared__ char smem[];
    const int tid = threadIdx.x;
    const int lid = tid & 31;
    const int wid = tid >> 5;
    const int wr  = wid >> 2;            // warp row 0..1 (64 rows)
    const int wc  = wid & 3;             // warp col 0..3 (32 cols)
    const int b   = blockIdx.y;

    // Decode upper-triangular pair index -> (ti, tj), ti <= tj.
    int ti = 0, rem = blockIdx.x;
    while (rem >= NTILES - ti) { rem -= NTILES - ti; ti++; }
    const int tj = ti + rem;
    const bool diag = (ti == tj);

    const uint32_t A_HI = OFF_A_HI, A_H8 = OFF_A_H8, A_L8 = OFF_A_L8;
    const uint32_t B_HI = diag ? A_HI : OFF_B_HI;
    const uint32_t B_H8 = diag ? A_H8 : OFF_B_H8;
    const uint32_t B_L8 = diag ? A_L8 : OFF_B_L8;

    // --- Stage operands ----------------------------------------------------
    {
        const uint4* hi4 = reinterpret_cast<const uint4*>(g_hi);
        const long baseA = ((long)b * M_PAD + (long)ti * TILE) * 8;   // uint4/row (bf16)
        const long baseB = ((long)b * M_PAD + (long)tj * TILE) * 8;
#pragma unroll
        for (int it = 0; it < 4; it++) {
            int idx = it * 256 + tid;        // 0..1023
            int row = idx >> 3, seg = idx & 7;
            int so = row * ROWB + seg * 16;
            *reinterpret_cast<uint4*>(smem + A_HI + so) = hi4[baseA + row * 8 + seg];
            if (!diag)
                *reinterpret_cast<uint4*>(smem + B_HI + so) = hi4[baseB + row * 8 + seg];
        }
        const uint4* h84 = reinterpret_cast<const uint4*>(g_h8);
        const uint4* l84 = reinterpret_cast<const uint4*>(g_l8);
        const long base8A = ((long)b * M_PAD + (long)ti * TILE) * 4;  // uint4/row (fp8)
        const long base8B = ((long)b * M_PAD + (long)tj * TILE) * 4;
#pragma unroll
        for (int it = 0; it < 2; it++) {
            int idx = it * 256 + tid;        // 0..511
            int row = idx >> 2, seg = idx & 3;
            int so = row * ROWB8 + seg * 16;
            *reinterpret_cast<uint4*>(smem + A_H8 + so) = h84[base8A + row * 4 + seg];
            *reinterpret_cast<uint4*>(smem + A_L8 + so) = l84[base8A + row * 4 + seg];
            if (!diag) {
                *reinterpret_cast<uint4*>(smem + B_H8 + so) = h84[base8B + row * 4 + seg];
                *reinterpret_cast<uint4*>(smem + B_L8 + so) = l84[base8B + row * 4 + seg];
            }
        }
    }
    __syncthreads();

    const uint32_t sb = smem_u32(smem);
    // bf16 lane offsets
    const uint32_t a_lane = (uint32_t)(wr * 64 + (lid & 15)) * ROWB + (lid >> 4) * 16;
    const uint32_t b_lane = (uint32_t)(wc * 32 + (lid & 15)) * ROWB + (lid >> 4) * 16;
    // fp8 lane offsets (pitch 80)
    const uint32_t a8_lane = (uint32_t)(wr * 64 + (lid & 15)) * ROWB8 + (lid >> 4) * 16;
    const uint32_t b8_lane = (uint32_t)(wc * 32 + (lid & 15)) * ROWB8 + (lid >> 4) * 16;

    float acc[4][4][4];
#pragma unroll
    for (int mt = 0; mt < 4; mt++)
#pragma unroll
        for (int nt = 0; nt < 4; nt++)
#pragma unroll
            for (int q = 0; q < 4; q++) acc[mt][nt][q] = 0.0f;

    // --- hh term: bf16, 4 x k16 -------------------------------------------
#pragma unroll
    for (int k = 0; k < 4; k++) {
        uint32_t af[4][4], bh[2][4];
#pragma unroll
        for (int mt = 0; mt < 4; mt++)
            ldsm_x4(af[mt], sb + A_HI + a_lane + mt * 16 * ROWB + k * 32);
#pragma unroll
        for (int bt = 0; bt < 2; bt++)
            ldsm_x4(bh[bt], sb + B_HI + b_lane + bt * 16 * ROWB + k * 32);
#pragma unroll
        for (int mt = 0; mt < 4; mt++)
#pragma unroll
            for (int nt = 0; nt < 4; nt++)
                mma16816(acc[mt][nt], af[mt],
                         bh[nt >> 1][nt & 1], bh[nt >> 1][(nt & 1) + 2]);
    }

    // --- cross terms: e4m3, 2 x k32 ---------------------------------------
    // Ah*Bl = A_h8 * B_l8 ; Al*Bh = A_l8 * B_h8  (scales 1/8 and 8 cancel)
#pragma unroll
    for (int s = 0; s < 2; s++) {
        uint32_t ah8[4][4], al8[4][4], bh8[2][4], bl8[2][4];
#pragma unroll
        for (int mt = 0; mt < 4; mt++) {
            ldsm_x4(ah8[mt], sb + A_H8 + a8_lane + mt * 16 * ROWB8 + s * 32);
            ldsm_x4(al8[mt], sb + A_L8 + a8_lane + mt * 16 * ROWB8 + s * 32);
        }
#pragma unroll
        for (int bt = 0; bt < 2; bt++) {
            ldsm_x4(bh8[bt], sb + B_H8 + b8_lane + bt * 16 * ROWB8 + s * 32);
            ldsm_x4(bl8[bt], sb + B_L8 + b8_lane + bt * 16 * ROWB8 + s * 32);
        }
#pragma unroll
        for (int mt = 0; mt < 4; mt++)
#pragma unroll
            for (int nt = 0; nt < 4; nt++) {
                // ldsm x4 over (16 rows, 2 k-halves): frags for 2 n-tiles:
                // even nt: b0=r0, b1=r2 ; odd nt: b0=r1, b1=r3
                mma16832_e4m3(acc[mt][nt], ah8[mt],
                              bl8[nt >> 1][nt & 1], bl8[nt >> 1][(nt & 1) + 2]);
                mma16832_e4m3(acc[mt][nt], al8[mt],
                              bh8[nt >> 1][nt & 1], bh8[nt >> 1][(nt & 1) + 2]);
            }
    }

    // Operand SMEM dead after this barrier.
    __syncthreads();

    // --- Epilogue (R3 style: direct frag stores + transpose for mirror) ----
    float* tile_s = reinterpret_cast<float*>(smem);   // [c][r], pitch TPITCH
    const int lrow0 = wr * 64 + (lid >> 2);
    const int lcol0 = wc * 32 + (lid & 3) * 2;
    const long M = M_OUT;
    float* const outb = out + (long)b * M * M;

#pragma unroll
    for (int mt = 0; mt < 4; mt++) {
#pragma unroll
        for (int nt = 0; nt < 4; nt++) {
            int lc = lcol0 + nt * 8;
#pragma unroll
            for (int h = 0; h < 2; h++) {
                int lr = lrow0 + mt * 16 + h * 8;
                float2 v;
                v.x = tanh_relu(acc[mt][nt][h * 2 + 0]);
                v.y = tanh_relu(acc[mt][nt][h * 2 + 1]);
                if (diag) {
                    if (lr == lc)     v.x += 0.5f;
                    if (lr == lc + 1) v.y += 0.5f;
                }
                int gr = ti * TILE + lr, gc = tj * TILE + lc;
                if (gr < M_OUT && gc < M_OUT)
                    *reinterpret_cast<float2*>(outb + (long)gr * M + gc) = v;
                if (!diag) {
                    tile_s[(lc + 0) * TPITCH + lr] = v.x;   // conflict-free
                    tile_s[(lc + 1) * TPITCH + lr] = v.y;
                }
            }
        }
    }

    if (!diag) {
        __syncthreads();
        // Mirror tile (tj, ti): coalesced float4 stores, conflict-free reads.
#pragma unroll
        for (int it = 0; it < 16; it++) {
            int e  = it * 256 + tid;           // 0..4095 float4 slots
            int c  = e >> 5;                   // 0..127
            int rq = e & 31;
            float4 w = *reinterpret_cast<float4*>(tile_s + c * TPITCH + rq * 4);
            int gr = tj * TILE + c;
            if (gr < M_OUT)
                *reinterpret_cast<float4*>(
                    outb + (long)gr * M + ti * TILE + rq * 4) = w;
        }
    }
}

// ---------------------------------------------------------------------------
extern "C" void kernel_launch(void* const* d_in, const int* in_sizes, int n_in,
                              void* d_out, int out_size) {
    const float* sp = (const float*)d_in[0];
    const float* tp = (const float*)d_in[1];
    if (n_in >= 2 && in_sizes[0] < in_sizes[1]) {
        sp = (const float*)d_in[1];
        tp = (const float*)d_in[0];
    }
    float* out = (float*)d_out;

    const int TOT = B_ * M_PAD * (KD / 4);
    convert_split_kernel<<<(TOT + 255) / 256, 256>>>(
        (const float4*)sp, (const float4*)tp);

    cudaFuncSetAttribute(gram_kernel,
                         cudaFuncAttributeMaxDynamicSharedMemorySize, SMEM_BYTES);
    dim3 grid(NPAIRS, B_);
    gram_kernel<<<grid, 256, SMEM_BYTES>>>(out);
}

// round 7
// speedup vs baseline: 1.0004x; 1.0004x over previous
#include <cuda_runtime.h>
#include <cuda_bf16.h>
#include <cstdint>

#define B_      16
#define N_SP    2048
#define N_TM    64
#define M_OUT   2112
#define M_PAD   2176
#define KD      64
#define TILE    128
#define NTILES  17
#define NPAIRS2 81       // sum over rows ti of ceil((17-ti)/2)

// Scratch: bf16 hi/lo splits of concatenated+padded node embeddings.
__device__ __nv_bfloat16 g_hi[B_ * M_PAD * KD];
__device__ __nv_bfloat16 g_lo[B_ * M_PAD * KD];

// ---------------------------------------------------------------------------
// Pass 1: fp32 -> bf16 hi/lo split, concat(spatial, temporal), zero-pad rows.
// ---------------------------------------------------------------------------
__global__ void convert_split_kernel(const float4* __restrict__ sp,
                                     const float4* __restrict__ tp) {
    const int TOT = B_ * M_PAD * (KD / 4);
    int idx = blockIdx.x * blockDim.x + threadIdx.x;
    if (idx >= TOT) return;
    int kq  = idx & 15;
    int row = (idx >> 4) % M_PAD;
    int b   = idx / (M_PAD * 16);

    float4 x = make_float4(0.f, 0.f, 0.f, 0.f);
    if (row < N_SP)
        x = sp[((long)b * N_SP + row) * 16 + kq];
    else if (row < M_OUT)
        x = tp[((long)b * N_TM + (row - N_SP)) * 16 + kq];

    float xf[4] = {x.x, x.y, x.z, x.w};
    union { __nv_bfloat16 h[4]; uint2 u; } uh;
    union { __nv_bfloat16 h[4]; uint2 u; } ul;
#pragma unroll
    for (int i = 0; i < 4; i++) {
        __nv_bfloat16 h = __float2bfloat16(xf[i]);
        float lo = xf[i] - __bfloat162float(h);
        uh.h[i] = h;
        ul.h[i] = __float2bfloat16(lo);
    }
    *reinterpret_cast<uint2*>(&g_hi[(long)idx * 4]) = uh.u;
    *reinterpret_cast<uint2*>(&g_lo[(long)idx * 4]) = ul.u;
}

// ---------------------------------------------------------------------------
// PTX helpers (portable compute_103: mma.sync + ldmatrix + tanh.approx)
// ---------------------------------------------------------------------------
__device__ __forceinline__ uint32_t smem_u32(const void* p) {
    uint32_t a;
    asm("{ .reg .u64 t; cvta.to.shared.u64 t, %1; cvt.u32.u64 %0, t; }"
        : "=r"(a) : "l"(p));
    return a;
}

__device__ __forceinline__ void ldsm_x4(uint32_t* r, uint32_t addr) {
    asm volatile("ldmatrix.sync.aligned.m8n8.x4.shared.b16 {%0,%1,%2,%3}, [%4];"
                 : "=r"(r[0]), "=r"(r[1]), "=r"(r[2]), "=r"(r[3]) : "r"(addr));
}

__device__ __forceinline__ void mma16816(float* c, const uint32_t* a,
                                         uint32_t b0, uint32_t b1) {
    asm volatile(
        "mma.sync.aligned.m16n8k16.row.col.f32.bf16.bf16.f32 "
        "{%0,%1,%2,%3}, {%4,%5,%6,%7}, {%8,%9}, {%0,%1,%2,%3};"
        : "+f"(c[0]), "+f"(c[1]), "+f"(c[2]), "+f"(c[3])
        : "r"(a[0]), "r"(a[1]), "r"(a[2]), "r"(a[3]), "r"(b0), "r"(b1));
}

__device__ __forceinline__ float tanh_relu(float x) {
    x = fmaxf(x, 0.0f);
    float y;
    asm("tanh.approx.f32 %0, %1;" : "=f"(y) : "f"(x));
    return y;
}

// ---------------------------------------------------------------------------
// Pass 2: one CTA (256 thr, 8 warps of 64x32) per PAIR of adjacent
// upper-triangular tiles sharing the A band: (ti, tjA) and (ti, tjA+1).
// Stage A once; run mainloop/epilogue twice reusing the accumulators.
// ---------------------------------------------------------------------------
#define ROWB       144                   // smem operand pitch (bytes)
#define TILE_B     (128 * ROWB)          // 18432 B per operand tile
#define OFF_A_HI   0
#define OFF_A_LO   (1 * TILE_B)
#define OFF_B1_HI  (2 * TILE_B)          // 36864
#define OFF_B1_LO  (3 * TILE_B)
#define OFF_B2_HI  (4 * TILE_B)          // 73728
#define OFF_B2_LO  (5 * TILE_B)
#define SMEM_BYTES (6 * TILE_B)          // 110592 (108 KB) -> 2 CTAs/SM
#define TPITCH     132                   // transpose pitch (floats)

__global__ void __launch_bounds__(256, 2)
gram_kernel(float* __restrict__ out) {
    extern __shared__ char smem[];
    const int tid = threadIdx.x;
    const int lid = tid & 31;
    const int wid = tid >> 5;
    const int wr  = wid >> 2;            // warp row 0..1 (64 rows)
    const int wc  = wid & 3;             // warp col 0..3 (32 cols)
    const int b   = blockIdx.y;

    // Decode pair index: row ti has ceil((17-ti)/2) pairs.
    int ti = 0, rem = blockIdx.x, P;
    while (rem >= (P = (18 - ti) >> 1)) { rem -= P; ti++; }
    const int  tjA  = ti + 2 * rem;
    const int  tjB  = tjA + 1;
    const bool diag = (rem == 0);        // first tile of the row is (ti,ti)
    const bool has2 = (tjB < NTILES);

    // --- Stage operand tiles ----------------------------------------------
    {
        const uint4* hi4 = reinterpret_cast<const uint4*>(g_hi);
        const uint4* lo4 = reinterpret_cast<const uint4*>(g_lo);
        const long baseA  = ((long)b * M_PAD + (long)ti  * TILE) * 8;
        const long baseB1 = ((long)b * M_PAD + (long)tjA * TILE) * 8;
        const long baseB2 = ((long)b * M_PAD + (long)tjB * TILE) * 8;
#pragma unroll
        for (int it = 0; it < 4; it++) {
            int idx = it * 256 + tid;        // 0..1023
            int row = idx >> 3, seg = idx & 7;
            int so = row * ROWB + seg * 16;
            long o = row * 8 + seg;
            *reinterpret_cast<uint4*>(smem + OFF_A_HI + so) = hi4[baseA + o];
            *reinterpret_cast<uint4*>(smem + OFF_A_LO + so) = lo4[baseA + o];
            if (!diag) {
                *reinterpret_cast<uint4*>(smem + OFF_B1_HI + so) = hi4[baseB1 + o];
                *reinterpret_cast<uint4*>(smem + OFF_B1_LO + so) = lo4[baseB1 + o];
            }
            if (has2) {
                *reinterpret_cast<uint4*>(smem + OFF_B2_HI + so) = hi4[baseB2 + o];
                *reinterpret_cast<uint4*>(smem + OFF_B2_LO + so) = lo4[baseB2 + o];
            }
        }
    }
    __syncthreads();

    const uint32_t sb = smem_u32(smem);
    const uint32_t a_lane = (uint32_t)(wr * 64 + (lid & 15)) * ROWB + (lid >> 4) * 16;
    const uint32_t b_lane = (uint32_t)(wc * 32 + (lid & 15)) * ROWB + (lid >> 4) * 16;
    const uint32_t aoff_h = sb + OFF_A_HI + a_lane;
    const uint32_t aoff_l = sb + OFF_A_LO + a_lane;

    float acc[4][4][4];
    float* const outb = out + (long)b * (long)M_OUT * M_OUT;
    const int lrow0 = wr * 64 + (lid >> 2);
    const int lcol0 = wc * 32 + (lid & 3) * 2;
    float* const buf = reinterpret_cast<float*>(smem + OFF_B1_HI);

    // bf16 3-split mainloop vs B tiles at (bhi, blo); fills acc.
    auto mainloop = [&](uint32_t bhi, uint32_t blo) {
#pragma unroll
        for (int mt = 0; mt < 4; mt++)
#pragma unroll
            for (int nt = 0; nt < 4; nt++)
#pragma unroll
                for (int q = 0; q < 4; q++) acc[mt][nt][q] = 0.0f;
#pragma unroll
        for (int k = 0; k < 4; k++) {
            uint32_t af[4][4], bh[2][4], bl[2][4];
#pragma unroll
            for (int mt = 0; mt < 4; mt++)
                ldsm_x4(af[mt], aoff_h + mt * 16 * ROWB + k * 32);
#pragma unroll
            for (int bt = 0; bt < 2; bt++) {
                ldsm_x4(bh[bt], bhi + b_lane + bt * 16 * ROWB + k * 32);
                ldsm_x4(bl[bt], blo + b_lane + bt * 16 * ROWB + k * 32);
            }
#pragma unroll
            for (int mt = 0; mt < 4; mt++)
#pragma unroll
                for (int nt = 0; nt < 4; nt++) {
                    mma16816(acc[mt][nt], af[mt],
                             bh[nt >> 1][nt & 1], bh[nt >> 1][(nt & 1) + 2]);
                    mma16816(acc[mt][nt], af[mt],
                             bl[nt >> 1][nt & 1], bl[nt >> 1][(nt & 1) + 2]);
                }
#pragma unroll
            for (int mt = 0; mt < 4; mt++)
                ldsm_x4(af[mt], aoff_l + mt * 16 * ROWB + k * 32);  // reuse af
#pragma unroll
            for (int mt = 0; mt < 4; mt++)
#pragma unroll
                for (int nt = 0; nt < 4; nt++)
                    mma16816(acc[mt][nt], af[mt],
                             bh[nt >> 1][nt & 1], bh[nt >> 1][(nt & 1) + 2]);
        }
    };

    // Activate in place (+diag) and store the direct tile (ti, tjX) from frags.
    auto activate_direct = [&](int tjX, bool addDiag) {
#pragma unroll
        for (int mt = 0; mt < 4; mt++)
#pragma unroll
            for (int nt = 0; nt < 4; nt++) {
                int lc = lcol0 + nt * 8;
#pragma unroll
                for (int h = 0; h < 2; h++) {
                    int lr = lrow0 + mt * 16 + h * 8;
                    float2 v;
                    v.x = tanh_relu(acc[mt][nt][h * 2 + 0]);
                    v.y = tanh_relu(acc[mt][nt][h * 2 + 1]);
                    if (addDiag) {
                        if (lr == lc)     v.x += 0.5f;
                        if (lr == lc + 1) v.y += 0.5f;
                    }
                    acc[mt][nt][h * 2 + 0] = v.x;   // keep for mirror
                    acc[mt][nt][h * 2 + 1] = v.y;
                    int gr = ti * TILE + lr, gc = tjX * TILE + lc;
                    if (gr < M_OUT && gc < M_OUT)
                        *reinterpret_cast<float2*>(
                            outb + (long)gr * M_OUT + gc) = v;
                }
            }
    };

    // Write this warp's activated frags transposed into buf (col range
    // [c0, c0+ncols)), buf layout [c - c0][r], pitch TPITCH.
    auto write_T = [&](int c0) {
#pragma unroll
        for (int mt = 0; mt < 4; mt++)
#pragma unroll
            for (int nt = 0; nt < 4; nt++) {
                int lc = lcol0 + nt * 8 - c0;
#pragma unroll
                for (int h = 0; h < 2; h++) {
                    int lr = lrow0 + mt * 16 + h * 8;
                    buf[(lc + 0) * TPITCH + lr] = acc[mt][nt][h * 2 + 0];
                    buf[(lc + 1) * TPITCH + lr] = acc[mt][nt][h * 2 + 1];
                }
            }
    };

    // Drain ncols columns of buf as mirror rows of tile (tjX, ti).
    auto drain_T = [&](int tjX, int c0, int ncols) {
        int slots = ncols * 32;            // float4 chunks
        for (int e = tid; e < slots; e += 256) {
            int c  = e >> 5;               // 0..ncols-1
            int rq = e & 31;
            float4 w = *reinterpret_cast<float4*>(buf + c * TPITCH + rq * 4);
            int gr = tjX * TILE + c0 + c;  // mirror cols ti*128+… always valid
            if (gr < M_OUT)
                *reinterpret_cast<float4*>(
                    outb + (long)gr * M_OUT + ti * TILE + rq * 4) = w;
        }
    };

    // ---- Tile 1: (ti, tjA) ------------------------------------------------
    mainloop(sb + (diag ? OFF_A_HI : OFF_B1_HI),
             sb + (diag ? OFF_A_LO : OFF_B1_LO));
    activate_direct(tjA, diag);
    if (!diag) {
        // Mirror via B1 region (36 KB): two 64-col half passes (B2 stays live).
        __syncthreads();                   // all warps done reading B1
        if (wc < 2) write_T(0);
        __syncthreads();
        drain_T(tjA, 0, 64);
        __syncthreads();
        if (wc >= 2) write_T(64);
        __syncthreads();
        drain_T(tjA, 64, 64);
    }

    // ---- Tile 2: (ti, tjB) ------------------------------------------------
    if (has2) {
        mainloop(sb + OFF_B2_HI, sb + OFF_B2_LO);
        activate_direct(tjB, false);       // tjB > ti: never diagonal
        __syncthreads();                   // all warps done reading A/B2 + drain
        write_T(0);                        // full 128-col buffer spans B1+B2
        __syncthreads();
        drain_T(tjB, 0, 128);
    }
}

// ---------------------------------------------------------------------------
extern "C" void kernel_launch(void* const* d_in, const int* in_sizes, int n_in,
                              void* d_out, int out_size) {
    const float* sp = (const float*)d_in[0];
    const float* tp = (const float*)d_in[1];
    if (n_in >= 2 && in_sizes[0] < in_sizes[1]) {
        sp = (const float*)d_in[1];
        tp = (const float*)d_in[0];
    }
    float* out = (float*)d_out;

    const int TOT = B_ * M_PAD * (KD / 4);
    convert_split_kernel<<<(TOT + 255) / 256, 256>>>(
        (const float4*)sp, (const float4*)tp);

    cudaFuncSetAttribute(gram_kernel,
                         cudaFuncAttributeMaxDynamicSharedMemorySize, SMEM_BYTES);
    dim3 grid(NPAIRS2, B_);
    gram_kernel<<<grid, 256, SMEM_BYTES>>>(out);
}

// round 8
// speedup vs baseline: 1.0429x; 1.0425x over previous
#include <cuda_runtime.h>
#include <cuda_bf16.h>
#include <cstdint>

#define B_      16
#define N_SP    2048
#define N_TM    64
#define M_OUT   2112
#define M_PAD   2176
#define KD      64
#define TILE    128
#define NTILES  17
#define NPAIRS  153      // 17*18/2 upper-triangular tile pairs

// Scratch: bf16 hi/lo splits of concatenated+padded node embeddings.
__device__ __nv_bfloat16 g_hi[B_ * M_PAD * KD];
__device__ __nv_bfloat16 g_lo[B_ * M_PAD * KD];

// ---------------------------------------------------------------------------
// Pass 1: fp32 -> bf16 hi/lo split, concat(spatial, temporal), zero-pad rows.
// ---------------------------------------------------------------------------
__global__ void convert_split_kernel(const float4* __restrict__ sp,
                                     const float4* __restrict__ tp) {
    const int TOT = B_ * M_PAD * (KD / 4);
    int idx = blockIdx.x * blockDim.x + threadIdx.x;
    if (idx >= TOT) return;
    int kq  = idx & 15;
    int row = (idx >> 4) % M_PAD;
    int b   = idx / (M_PAD * 16);

    float4 x = make_float4(0.f, 0.f, 0.f, 0.f);
    if (row < N_SP)
        x = sp[((long)b * N_SP + row) * 16 + kq];
    else if (row < M_OUT)
        x = tp[((long)b * N_TM + (row - N_SP)) * 16 + kq];

    float xf[4] = {x.x, x.y, x.z, x.w};
    union { __nv_bfloat16 h[4]; uint2 u; } uh;
    union { __nv_bfloat16 h[4]; uint2 u; } ul;
#pragma unroll
    for (int i = 0; i < 4; i++) {
        __nv_bfloat16 h = __float2bfloat16(xf[i]);
        float lo = xf[i] - __bfloat162float(h);
        uh.h[i] = h;
        ul.h[i] = __float2bfloat16(lo);
    }
    *reinterpret_cast<uint2*>(&g_hi[(long)idx * 4]) = uh.u;
    *reinterpret_cast<uint2*>(&g_lo[(long)idx * 4]) = ul.u;
}

// ---------------------------------------------------------------------------
// PTX helpers (portable compute_103: mma.sync + ldmatrix + tanh.approx)
// ---------------------------------------------------------------------------
__device__ __forceinline__ uint32_t smem_u32(const void* p) {
    uint32_t a;
    asm("{ .reg .u64 t; cvta.to.shared.u64 t, %1; cvt.u32.u64 %0, t; }"
        : "=r"(a) : "l"(p));
    return a;
}

__device__ __forceinline__ void ldsm_x4(uint32_t* r, uint32_t addr) {
    asm volatile("ldmatrix.sync.aligned.m8n8.x4.shared.b16 {%0,%1,%2,%3}, [%4];"
                 : "=r"(r[0]), "=r"(r[1]), "=r"(r[2]), "=r"(r[3]) : "r"(addr));
}

__device__ __forceinline__ void mma16816(float* c, const uint32_t* a,
                                         uint32_t b0, uint32_t b1) {
    asm volatile(
        "mma.sync.aligned.m16n8k16.row.col.f32.bf16.bf16.f32 "
        "{%0,%1,%2,%3}, {%4,%5,%6,%7}, {%8,%9}, {%0,%1,%2,%3};"
        : "+f"(c[0]), "+f"(c[1]), "+f"(c[2]), "+f"(c[3])
        : "r"(a[0]), "r"(a[1]), "r"(a[2]), "r"(a[3]), "r"(b0), "r"(b1));
}

__device__ __forceinline__ float tanh_relu(float x) {
    x = fmaxf(x, 0.0f);
    float y;
    asm("tanh.approx.f32 %0, %1;" : "=f"(y) : "f"(x));
    return y;
}

// ---------------------------------------------------------------------------
// Pass 2: one CTA (512 thr, 16 warps of 32x32) per upper-triangular 128x128
// tile pair. 32 accumulators/thread -> 64 regs -> 2 CTAs = 32 warps/SM.
// ---------------------------------------------------------------------------
#define ROWB       144                   // smem operand pitch (bytes)
#define TILE_B     (128 * ROWB)          // 18432 B per operand tile
#define SMEM_BYTES (4 * TILE_B)          // 73728 B (covers transpose buffer)
#define TPITCH     132                   // transpose pitch (floats)

__global__ void __launch_bounds__(512, 2)
gram_kernel(float* __restrict__ out) {
    extern __shared__ char smem[];
    const int tid = threadIdx.x;
    const int lid = tid & 31;
    const int wid = tid >> 5;            // 0..15
    const int wr  = wid >> 2;            // warp row 0..3 (32 rows)
    const int wc  = wid & 3;             // warp col 0..3 (32 cols)
    const int b   = blockIdx.y;

    // Decode upper-triangular pair index -> (ti, tj), ti <= tj.
    int ti = 0, rem = blockIdx.x;
    while (rem >= NTILES - ti) { rem -= NTILES - ti; ti++; }
    const int tj = ti + rem;
    const bool diag = (ti == tj);

    const uint32_t A_HI = 0, A_LO = TILE_B;
    const uint32_t B_HI = diag ? A_HI : 2u * TILE_B;
    const uint32_t B_LO = diag ? A_LO : 3u * TILE_B;

    // --- Stage operand tiles (128 rows x 128B payload, 144B pitch) ---------
    {
        const uint4* hi4 = reinterpret_cast<const uint4*>(g_hi);
        const uint4* lo4 = reinterpret_cast<const uint4*>(g_lo);
        const long baseA = ((long)b * M_PAD + (long)ti * TILE) * 8;
        const long baseB = ((long)b * M_PAD + (long)tj * TILE) * 8;
#pragma unroll
        for (int it = 0; it < 2; it++) {
            int idx = it * 512 + tid;        // 0..1023
            int row = idx >> 3, seg = idx & 7;
            int so = row * ROWB + seg * 16;
            long offA = baseA + row * 8 + seg;
            *reinterpret_cast<uint4*>(smem + A_HI + so) = hi4[offA];
            *reinterpret_cast<uint4*>(smem + A_LO + so) = lo4[offA];
            if (!diag) {
                long offB = baseB + row * 8 + seg;
                *reinterpret_cast<uint4*>(smem + B_HI + so) = hi4[offB];
                *reinterpret_cast<uint4*>(smem + B_LO + so) = lo4[offB];
            }
        }
    }
    __syncthreads();

    const uint32_t sb = smem_u32(smem);
    const uint32_t a_lane = (uint32_t)(wr * 32 + (lid & 15)) * ROWB + (lid >> 4) * 16;
    const uint32_t b_lane = (uint32_t)(wc * 32 + (lid & 15)) * ROWB + (lid >> 4) * 16;
    const uint32_t aoff_h = sb + A_HI + a_lane;
    const uint32_t aoff_l = sb + A_LO + a_lane;
    const uint32_t boff_h = sb + B_HI + b_lane;
    const uint32_t boff_l = sb + B_LO + b_lane;

    float acc[2][4][4];
#pragma unroll
    for (int mt = 0; mt < 2; mt++)
#pragma unroll
        for (int nt = 0; nt < 4; nt++)
#pragma unroll
            for (int q = 0; q < 4; q++) acc[mt][nt][q] = 0.0f;

    // Mainloop per k16: 8 ldsm.x4 -> 24 mma.
    // Order: Ah x Bh; Ah x Bl; then Al overwrites af -> Al x Bh.
#pragma unroll
    for (int k = 0; k < 4; k++) {
        uint32_t af[2][4], bh[2][4], bl[2][4];
#pragma unroll
        for (int mt = 0; mt < 2; mt++)
            ldsm_x4(af[mt], aoff_h + mt * 16 * ROWB + k * 32);
#pragma unroll
        for (int bt = 0; bt < 2; bt++)
            ldsm_x4(bh[bt], boff_h + bt * 16 * ROWB + k * 32);
#pragma unroll
        for (int mt = 0; mt < 2; mt++)
#pragma unroll
            for (int nt = 0; nt < 4; nt++)
                mma16816(acc[mt][nt], af[mt],
                         bh[nt >> 1][nt & 1], bh[nt >> 1][(nt & 1) + 2]);
#pragma unroll
        for (int bt = 0; bt < 2; bt++)
            ldsm_x4(bl[bt], boff_l + bt * 16 * ROWB + k * 32);
#pragma unroll
        for (int mt = 0; mt < 2; mt++)
#pragma unroll
            for (int nt = 0; nt < 4; nt++)
                mma16816(acc[mt][nt], af[mt],
                         bl[nt >> 1][nt & 1], bl[nt >> 1][(nt & 1) + 2]);
#pragma unroll
        for (int mt = 0; mt < 2; mt++)
            ldsm_x4(af[mt], aoff_l + mt * 16 * ROWB + k * 32);   // af := Al
#pragma unroll
        for (int mt = 0; mt < 2; mt++)
#pragma unroll
            for (int nt = 0; nt < 4; nt++)
                mma16816(acc[mt][nt], af[mt],
                         bh[nt >> 1][nt & 1], bh[nt >> 1][(nt & 1) + 2]);
    }

    // Operand SMEM dead after this barrier.
    __syncthreads();

    // --- Epilogue: direct frag stores + transpose for the mirror tile ------
    float* tile_s = reinterpret_cast<float*>(smem);   // [c][r], pitch TPITCH
    const int lrow0 = wr * 32 + (lid >> 2);
    const int lcol0 = wc * 32 + (lid & 3) * 2;
    const long M = M_OUT;
    float* const outb = out + (long)b * M * M;

#pragma unroll
    for (int mt = 0; mt < 2; mt++) {
#pragma unroll
        for (int nt = 0; nt < 4; nt++) {
            int lc = lcol0 + nt * 8;
#pragma unroll
            for (int h = 0; h < 2; h++) {
                int lr = lrow0 + mt * 16 + h * 8;
                float2 v;
                v.x = tanh_relu(acc[mt][nt][h * 2 + 0]);
                v.y = tanh_relu(acc[mt][nt][h * 2 + 1]);
                if (diag) {
                    if (lr == lc)     v.x += 0.5f;
                    if (lr == lc + 1) v.y += 0.5f;
                }
                int gr = ti * TILE + lr, gc = tj * TILE + lc;
                if (gr < M_OUT && gc < M_OUT)
                    *reinterpret_cast<float2*>(outb + (long)gr * M + gc) = v;
                if (!diag) {                   // transposed copy, conflict-free
                    tile_s[(lc + 0) * TPITCH + lr] = v.x;
                    tile_s[(lc + 1) * TPITCH + lr] = v.y;
                }
            }
        }
    }

    if (!diag) {
        __syncthreads();
        // Mirror tile (tj, ti): coalesced float4 stores, conflict-free reads.
#pragma unroll
        for (int it = 0; it < 8; it++) {
            int e  = it * 512 + tid;           // 0..4095 float4 slots
            int c  = e >> 5;                   // 0..127
            int rq = e & 31;
            float4 w = *reinterpret_cast<float4*>(tile_s + c * TPITCH + rq * 4);
            int gr = tj * TILE + c;
            if (gr < M_OUT)
                *reinterpret_cast<float4*>(
                    outb + (long)gr * M + ti * TILE + rq * 4) = w;
        }
    }
}

// ---------------------------------------------------------------------------
extern "C" void kernel_launch(void* const* d_in, const int* in_sizes, int n_in,
                              void* d_out, int out_size) {
    const float* sp = (const float*)d_in[0];
    const float* tp = (const float*)d_in[1];
    if (n_in >= 2 && in_sizes[0] < in_sizes[1]) {
        sp = (const float*)d_in[1];
        tp = (const float*)d_in[0];
    }
    float* out = (float*)d_out;

    const int TOT = B_ * M_PAD * (KD / 4);
    convert_split_kernel<<<(TOT + 255) / 256, 256>>>(
        (const float4*)sp, (const float4*)tp);

    cudaFuncSetAttribute(gram_kernel,
                         cudaFuncAttributeMaxDynamicSharedMemorySize, SMEM_BYTES);
    dim3 grid(NPAIRS, B_);
    gram_kernel<<<grid, 512, SMEM_BYTES>>>(out);
}

// round 9
// speedup vs baseline: 1.0483x; 1.0052x over previous
#include <cuda_runtime.h>
#include <cuda_bf16.h>
#include <cstdint>

#define B_      16
#define N_SP    2048
#define N_TM    64
#define M_OUT   2112
#define TILE    128
#define NTILES  17
#define NPAIRS  153      // 17*18/2 upper-triangular tile pairs

// ---------------------------------------------------------------------------
// PTX helpers (portable compute_103: mma.sync + ldmatrix + tanh.approx)
// ---------------------------------------------------------------------------
__device__ __forceinline__ uint32_t smem_u32(const void* p) {
    uint32_t a;
    asm("{ .reg .u64 t; cvta.to.shared.u64 t, %1; cvt.u32.u64 %0, t; }"
        : "=r"(a) : "l"(p));
    return a;
}

__device__ __forceinline__ void ldsm_x4(uint32_t* r, uint32_t addr) {
    asm volatile("ldmatrix.sync.aligned.m8n8.x4.shared.b16 {%0,%1,%2,%3}, [%4];"
                 : "=r"(r[0]), "=r"(r[1]), "=r"(r[2]), "=r"(r[3]) : "r"(addr));
}

__device__ __forceinline__ void mma16816(float* c, const uint32_t* a,
                                         uint32_t b0, uint32_t b1) {
    asm volatile(
        "mma.sync.aligned.m16n8k16.row.col.f32.bf16.bf16.f32 "
        "{%0,%1,%2,%3}, {%4,%5,%6,%7}, {%8,%9}, {%0,%1,%2,%3};"
        : "+f"(c[0]), "+f"(c[1]), "+f"(c[2]), "+f"(c[3])
        : "r"(a[0]), "r"(a[1]), "r"(a[2]), "r"(a[3]), "r"(b0), "r"(b1));
}

__device__ __forceinline__ float tanh_relu(float x) {
    x = fmaxf(x, 0.0f);
    float y;
    asm("tanh.approx.f32 %0, %1;" : "=f"(y) : "f"(x));
    return y;
}

// Streaming (evict-first) stores: output is write-once, keep L2 for operands.
__device__ __forceinline__ void stcs2(float* p, float2 v) {
    asm volatile("st.global.cs.v2.f32 [%0], {%1, %2};"
                 :: "l"(p), "f"(v.x), "f"(v.y) : "memory");
}
__device__ __forceinline__ void stcs4(float* p, float4 v) {
    asm volatile("st.global.cs.v4.f32 [%0], {%1, %2, %3, %4};"
                 :: "l"(p), "f"(v.x), "f"(v.y), "f"(v.z), "f"(v.w) : "memory");
}

// Split 8 fp32 -> packed bf16 hi (uint4) and lo (uint4).
__device__ __forceinline__ void split8(const float* xf, uint4& hv, uint4& lv) {
    union { __nv_bfloat16 h[8]; uint4 u; } uh;
    union { __nv_bfloat16 h[8]; uint4 u; } ul;
#pragma unroll
    for (int i = 0; i < 8; i++) {
        __nv_bfloat16 h = __float2bfloat16(xf[i]);
        float lo = xf[i] - __bfloat162float(h);
        uh.h[i] = h;
        ul.h[i] = __float2bfloat16(lo);
    }
    hv = uh.u;
    lv = ul.u;
}

// ---------------------------------------------------------------------------
// One CTA (256 thr, 8 warps of 64x32) per upper-triangular 128x128 tile pair.
// Staging loads fp32 directly (concat + pad) and splits hi/lo in-register.
// Mainloop: bf16 3-split gram with A-fragment reuse. Epilogue: direct frag
// stores + conflict-free SMEM transpose for the mirror tile. All stores .cs.
// ---------------------------------------------------------------------------
#define ROWB       144                   // smem operand pitch (bytes)
#define TILE_B     (128 * ROWB)          // 18432 B per operand tile
#define SMEM_BYTES (4 * TILE_B)          // 73728 B (covers transpose buffer)
#define TPITCH     132                   // transpose pitch (floats)

__global__ void __launch_bounds__(256, 2)
gram_kernel(const float4* __restrict__ sp, const float4* __restrict__ tp,
            float* __restrict__ out) {
    extern __shared__ char smem[];
    const int tid = threadIdx.x;
    const int lid = tid & 31;
    const int wid = tid >> 5;
    const int wr  = wid >> 2;            // warp row 0..1 (64 rows)
    const int wc  = wid & 3;             // warp col 0..3 (32 cols)
    const int b   = blockIdx.y;

    // Decode upper-triangular pair index -> (ti, tj), ti <= tj.
    int ti = 0, rem = blockIdx.x;
    while (rem >= NTILES - ti) { rem -= NTILES - ti; ti++; }
    const int tj = ti + rem;
    const bool diag = (ti == tj);

    const uint32_t A_HI = 0, A_LO = TILE_B;
    const uint32_t B_HI = diag ? A_HI : 2u * TILE_B;
    const uint32_t B_LO = diag ? A_LO : 3u * TILE_B;

    // --- Stage: load fp32, split hi/lo in-register, STS (pitch 144) --------
    {
#pragma unroll
        for (int it = 0; it < 4; it++) {
            int idx = it * 256 + tid;        // 0..1023
            int row = idx >> 3;              // 0..127
            int seg = idx & 7;               // 8-col segment
            int so  = row * ROWB + seg * 16;

#pragma unroll
            for (int side = 0; side < 2; side++) {
                if (side == 1 && diag) break;
                int t0   = side ? tj : ti;
                int grow = t0 * TILE + row;
                float4 x0 = make_float4(0.f, 0.f, 0.f, 0.f), x1 = x0;
                if (grow < N_SP) {
                    const float4* p = sp + ((long)b * N_SP + grow) * 16 + seg * 2;
                    x0 = p[0]; x1 = p[1];
                } else if (grow < M_OUT) {
                    const float4* p = tp + ((long)b * N_TM + (grow - N_SP)) * 16 + seg * 2;
                    x0 = p[0]; x1 = p[1];
                }
                float xf[8] = {x0.x, x0.y, x0.z, x0.w, x1.x, x1.y, x1.z, x1.w};
                uint4 hv, lv;
                split8(xf, hv, lv);
                uint32_t offH = side ? B_HI : A_HI;
                uint32_t offL = side ? B_LO : A_LO;
                *reinterpret_cast<uint4*>(smem + offH + so) = hv;
                *reinterpret_cast<uint4*>(smem + offL + so) = lv;
            }
        }
    }
    __syncthreads();

    const uint32_t sb = smem_u32(smem);
    const uint32_t a_lane = (uint32_t)(wr * 64 + (lid & 15)) * ROWB + (lid >> 4) * 16;
    const uint32_t b_lane = (uint32_t)(wc * 32 + (lid & 15)) * ROWB + (lid >> 4) * 16;
    const uint32_t aoff_h = sb + A_HI + a_lane;
    const uint32_t aoff_l = sb + A_LO + a_lane;
    const uint32_t boff_h = sb + B_HI + b_lane;
    const uint32_t boff_l = sb + B_LO + b_lane;

    float acc[4][4][4];
#pragma unroll
    for (int mt = 0; mt < 4; mt++)
#pragma unroll
        for (int nt = 0; nt < 4; nt++)
#pragma unroll
            for (int q = 0; q < 4; q++) acc[mt][nt][q] = 0.0f;

    // Mainloop: acc += Ah*Bh + Ah*Bl + Al*Bh (A fragments reused for 2 of 3)
#pragma unroll
    for (int k = 0; k < 4; k++) {
        uint32_t af[4][4], bh[2][4], bl[2][4];
#pragma unroll
        for (int mt = 0; mt < 4; mt++)
            ldsm_x4(af[mt], aoff_h + mt * 16 * ROWB + k * 32);
#pragma unroll
        for (int bt = 0; bt < 2; bt++) {
            ldsm_x4(bh[bt], boff_h + bt * 16 * ROWB + k * 32);
            ldsm_x4(bl[bt], boff_l + bt * 16 * ROWB + k * 32);
        }
#pragma unroll
        for (int mt = 0; mt < 4; mt++)
#pragma unroll
            for (int nt = 0; nt < 4; nt++) {
                mma16816(acc[mt][nt], af[mt],
                         bh[nt >> 1][nt & 1], bh[nt >> 1][(nt & 1) + 2]);
                mma16816(acc[mt][nt], af[mt],
                         bl[nt >> 1][nt & 1], bl[nt >> 1][(nt & 1) + 2]);
            }
#pragma unroll
        for (int mt = 0; mt < 4; mt++)
            ldsm_x4(af[mt], aoff_l + mt * 16 * ROWB + k * 32);   // reuse af
#pragma unroll
        for (int mt = 0; mt < 4; mt++)
#pragma unroll
            for (int nt = 0; nt < 4; nt++)
                mma16816(acc[mt][nt], af[mt],
                         bh[nt >> 1][nt & 1], bh[nt >> 1][(nt & 1) + 2]);
    }

    // Operand SMEM is dead after ALL warps pass this barrier.
    __syncthreads();

    // --- Epilogue ----------------------------------------------------------
    float* tile_s = reinterpret_cast<float*>(smem);   // [c][r], pitch TPITCH
    const int lrow0 = wr * 64 + (lid >> 2);
    const int lcol0 = wc * 32 + (lid & 3) * 2;
    const long M = M_OUT;
    float* const outb = out + (long)b * M * M;

#pragma unroll
    for (int mt = 0; mt < 4; mt++) {
#pragma unroll
        for (int nt = 0; nt < 4; nt++) {
            int lc = lcol0 + nt * 8;
#pragma unroll
            for (int h = 0; h < 2; h++) {
                int lr = lrow0 + mt * 16 + h * 8;
                float2 v;
                v.x = tanh_relu(acc[mt][nt][h * 2 + 0]);
                v.y = tanh_relu(acc[mt][nt][h * 2 + 1]);
                if (diag) {                    // self loops live on diag tiles
                    if (lr == lc)     v.x += 0.5f;
                    if (lr == lc + 1) v.y += 0.5f;
                }
                int gr = ti * TILE + lr, gc = tj * TILE + lc;
                if (gr < M_OUT && gc < M_OUT)
                    stcs2(outb + (long)gr * M + gc, v);
                if (!diag) {                   // transposed copy for mirror
                    tile_s[(lc + 0) * TPITCH + lr] = v.x;   // conflict-free
                    tile_s[(lc + 1) * TPITCH + lr] = v.y;
                }
            }
        }
    }

    if (!diag) {
        __syncthreads();
        // Mirror tile (tj, ti): coalesced float4 stores; conflict-free reads.
#pragma unroll
        for (int it = 0; it < 16; it++) {
            int e  = it * 256 + tid;           // 0..4095 float4 slots
            int c  = e >> 5;                   // 0..127
            int rq = e & 31;
            float4 w = *reinterpret_cast<float4*>(tile_s + c * TPITCH + rq * 4);
            int gr = tj * TILE + c;            // mirror cols always < M_OUT
            if (gr < M_OUT)
                stcs4(outb + (long)gr * M + ti * TILE + rq * 4, w);
        }
    }
}

// ---------------------------------------------------------------------------
extern "C" void kernel_launch(void* const* d_in, const int* in_sizes, int n_in,
                              void* d_out, int out_size) {
    const float* sp = (const float*)d_in[0];
    const float* tp = (const float*)d_in[1];
    if (n_in >= 2 && in_sizes[0] < in_sizes[1]) {   // defensive order check
        sp = (const float*)d_in[1];
        tp = (const float*)d_in[0];
    }
    float* out = (float*)d_out;

    cudaFuncSetAttribute(gram_kernel,
                         cudaFuncAttributeMaxDynamicSharedMemorySize, SMEM_BYTES);
    dim3 grid(NPAIRS, B_);
    gram_kernel<<<grid, 256, SMEM_BYTES>>>(
        (const float4*)sp, (const float4*)tp, out);
}

// round 10
// speedup vs baseline: 1.1581x; 1.1047x over previous
#include <cuda_runtime.h>
#include <cuda_bf16.h>
#include <cstdint>

#define B_      16
#define N_SP    2048
#define N_TM    64
#define M_OUT   2112
#define M_PAD   2176
#define KD      64
#define TILE    128
#define NTILES  17
#define NPAIRS  153      // 17*18/2 upper-triangular tile pairs

// Scratch: bf16 hi/lo splits of concatenated+padded node embeddings.
__device__ __nv_bfloat16 g_hi[B_ * M_PAD * KD];
__device__ __nv_bfloat16 g_lo[B_ * M_PAD * KD];

// ---------------------------------------------------------------------------
// Pass 1: fp32 -> bf16 hi/lo split, concat(spatial, temporal), zero-pad rows.
// ---------------------------------------------------------------------------
__global__ void convert_split_kernel(const float4* __restrict__ sp,
                                     const float4* __restrict__ tp) {
    const int TOT = B_ * M_PAD * (KD / 4);
    int idx = blockIdx.x * blockDim.x + threadIdx.x;
    if (idx >= TOT) return;
    int kq  = idx & 15;
    int row = (idx >> 4) % M_PAD;
    int b   = idx / (M_PAD * 16);

    float4 x = make_float4(0.f, 0.f, 0.f, 0.f);
    if (row < N_SP)
        x = sp[((long)b * N_SP + row) * 16 + kq];
    else if (row < M_OUT)
        x = tp[((long)b * N_TM + (row - N_SP)) * 16 + kq];

    float xf[4] = {x.x, x.y, x.z, x.w};
    union { __nv_bfloat16 h[4]; uint2 u; } uh;
    union { __nv_bfloat16 h[4]; uint2 u; } ul;
#pragma unroll
    for (int i = 0; i < 4; i++) {
        __nv_bfloat16 h = __float2bfloat16(xf[i]);
        float lo = xf[i] - __bfloat162float(h);
        uh.h[i] = h;
        ul.h[i] = __float2bfloat16(lo);
    }
    *reinterpret_cast<uint2*>(&g_hi[(long)idx * 4]) = uh.u;
    *reinterpret_cast<uint2*>(&g_lo[(long)idx * 4]) = ul.u;
}

// ---------------------------------------------------------------------------
// PTX helpers (portable compute_103: mma.sync + ldmatrix + cp.async + tanh)
// ---------------------------------------------------------------------------
__device__ __forceinline__ uint32_t smem_u32(const void* p) {
    uint32_t a;
    asm("{ .reg .u64 t; cvta.to.shared.u64 t, %1; cvt.u32.u64 %0, t; }"
        : "=r"(a) : "l"(p));
    return a;
}

__device__ __forceinline__ void cp_async16(uint32_t saddr, const void* gptr) {
    asm volatile("cp.async.ca.shared.global [%0], [%1], 16;"
                 :: "r"(saddr), "l"(gptr) : "memory");
}

__device__ __forceinline__ void cp_async_wait_all() {
    asm volatile("cp.async.commit_group;" ::: "memory");
    asm volatile("cp.async.wait_group 0;" ::: "memory");
}

__device__ __forceinline__ void ldsm_x4(uint32_t* r, uint32_t addr) {
    asm volatile("ldmatrix.sync.aligned.m8n8.x4.shared.b16 {%0,%1,%2,%3}, [%4];"
                 : "=r"(r[0]), "=r"(r[1]), "=r"(r[2]), "=r"(r[3]) : "r"(addr));
}

__device__ __forceinline__ void mma16816(float* c, const uint32_t* a,
                                         uint32_t b0, uint32_t b1) {
    asm volatile(
        "mma.sync.aligned.m16n8k16.row.col.f32.bf16.bf16.f32 "
        "{%0,%1,%2,%3}, {%4,%5,%6,%7}, {%8,%9}, {%0,%1,%2,%3};"
        : "+f"(c[0]), "+f"(c[1]), "+f"(c[2]), "+f"(c[3])
        : "r"(a[0]), "r"(a[1]), "r"(a[2]), "r"(a[3]), "r"(b0), "r"(b1));
}

__device__ __forceinline__ float tanh_relu(float x) {
    x = fmaxf(x, 0.0f);
    float y;
    asm("tanh.approx.f32 %0, %1;" : "=f"(y) : "f"(x));
    return y;
}

// ---------------------------------------------------------------------------
// Pass 2: one CTA (256 thr, 8 warps of 64x32) per upper-triangular 128x128
// tile pair. bf16 3-split gram; mirror tile via conflict-free SMEM transpose.
// Staging via cp.async (no LDG->reg->STS round trip in the prologue).
// ---------------------------------------------------------------------------
#define ROWB       144                   // smem operand pitch (bytes)
#define TILE_B     (128 * ROWB)          // 18432 B per operand tile
#define SMEM_BYTES (4 * TILE_B)          // 73728 B (covers transpose buffer)
#define TPITCH     132                   // transpose pitch (floats)

__global__ void __launch_bounds__(256, 2)
gram_kernel(float* __restrict__ out) {
    extern __shared__ char smem[];
    const int tid = threadIdx.x;
    const int lid = tid & 31;
    const int wid = tid >> 5;
    const int wr  = wid >> 2;            // warp row 0..1 (64 rows)
    const int wc  = wid & 3;             // warp col 0..3 (32 cols)
    const int b   = blockIdx.y;

    // Decode upper-triangular pair index -> (ti, tj), ti <= tj.
    int ti = 0, rem = blockIdx.x;
    while (rem >= NTILES - ti) { rem -= NTILES - ti; ti++; }
    const int tj = ti + rem;
    const bool diag = (ti == tj);

    const uint32_t A_HI = 0, A_LO = TILE_B;
    const uint32_t B_HI = diag ? A_HI : 2u * TILE_B;
    const uint32_t B_LO = diag ? A_LO : 3u * TILE_B;

    const uint32_t sb = smem_u32(smem);

    // --- Stage operand tiles via cp.async (128 rows x 128B, pitch 144) -----
    {
        const uint4* hi4 = reinterpret_cast<const uint4*>(g_hi);
        const uint4* lo4 = reinterpret_cast<const uint4*>(g_lo);
        const long baseA = ((long)b * M_PAD + (long)ti * TILE) * 8;
        const long baseB = ((long)b * M_PAD + (long)tj * TILE) * 8;
#pragma unroll
        for (int it = 0; it < 4; it++) {
            int idx = it * 256 + tid;        // 0..1023
            int row = idx >> 3, seg = idx & 7;
            uint32_t so = (uint32_t)(row * ROWB + seg * 16);
            long offA = baseA + row * 8 + seg;
            cp_async16(sb + A_HI + so, hi4 + offA);
            cp_async16(sb + A_LO + so, lo4 + offA);
            if (!diag) {
                long offB = baseB + row * 8 + seg;
                cp_async16(sb + B_HI + so, hi4 + offB);
                cp_async16(sb + B_LO + so, lo4 + offB);
            }
        }
    }
    cp_async_wait_all();
    __syncthreads();

    const uint32_t a_lane = (uint32_t)(wr * 64 + (lid & 15)) * ROWB + (lid >> 4) * 16;
    const uint32_t b_lane = (uint32_t)(wc * 32 + (lid & 15)) * ROWB + (lid >> 4) * 16;
    const uint32_t aoff_h = sb + A_HI + a_lane;
    const uint32_t aoff_l = sb + A_LO + a_lane;
    const uint32_t boff_h = sb + B_HI + b_lane;
    const uint32_t boff_l = sb + B_LO + b_lane;

    float acc[4][4][4];
#pragma unroll
    for (int mt = 0; mt < 4; mt++)
#pragma unroll
        for (int nt = 0; nt < 4; nt++)
#pragma unroll
            for (int q = 0; q < 4; q++) acc[mt][nt][q] = 0.0f;

    // Mainloop: acc += Ah*Bh + Ah*Bl + Al*Bh (A fragments reused for 2 of 3)
#pragma unroll
    for (int k = 0; k < 4; k++) {
        uint32_t af[4][4], bh[2][4], bl[2][4];
#pragma unroll
        for (int mt = 0; mt < 4; mt++)
            ldsm_x4(af[mt], aoff_h + mt * 16 * ROWB + k * 32);
#pragma unroll
        for (int bt = 0; bt < 2; bt++) {
            ldsm_x4(bh[bt], boff_h + bt * 16 * ROWB + k * 32);
            ldsm_x4(bl[bt], boff_l + bt * 16 * ROWB + k * 32);
        }
#pragma unroll
        for (int mt = 0; mt < 4; mt++)
#pragma unroll
            for (int nt = 0; nt < 4; nt++) {
                mma16816(acc[mt][nt], af[mt],
                         bh[nt >> 1][nt & 1], bh[nt >> 1][(nt & 1) + 2]);
                mma16816(acc[mt][nt], af[mt],
                         bl[nt >> 1][nt & 1], bl[nt >> 1][(nt & 1) + 2]);
            }
#pragma unroll
        for (int mt = 0; mt < 4; mt++)
            ldsm_x4(af[mt], aoff_l + mt * 16 * ROWB + k * 32);   // reuse af
#pragma unroll
        for (int mt = 0; mt < 4; mt++)
#pragma unroll
            for (int nt = 0; nt < 4; nt++)
                mma16816(acc[mt][nt], af[mt],
                         bh[nt >> 1][nt & 1], bh[nt >> 1][(nt & 1) + 2]);
    }

    // Operand SMEM is dead after ALL warps pass this barrier.
    __syncthreads();

    // --- Epilogue ----------------------------------------------------------
    float* tile_s = reinterpret_cast<float*>(smem);   // [c][r], pitch TPITCH
    const int lrow0 = wr * 64 + (lid >> 2);
    const int lcol0 = wc * 32 + (lid & 3) * 2;
    const long M = M_OUT;
    float* const outb = out + (long)b * M * M;

#pragma unroll
    for (int mt = 0; mt < 4; mt++) {
#pragma unroll
        for (int nt = 0; nt < 4; nt++) {
            int lc = lcol0 + nt * 8;
#pragma unroll
            for (int h = 0; h < 2; h++) {
                int lr = lrow0 + mt * 16 + h * 8;
                float2 v;
                v.x = tanh_relu(acc[mt][nt][h * 2 + 0]);
                v.y = tanh_relu(acc[mt][nt][h * 2 + 1]);
                if (diag) {                    // self loops live on diag tiles
                    if (lr == lc)     v.x += 0.5f;
                    if (lr == lc + 1) v.y += 0.5f;
                }
                int gr = ti * TILE + lr, gc = tj * TILE + lc;
                if (gr < M_OUT && gc < M_OUT)
                    *reinterpret_cast<float2*>(outb + (long)gr * M + gc) = v;
                if (!diag) {                   // transposed copy for mirror
                    tile_s[(lc + 0) * TPITCH + lr] = v.x;   // conflict-free
                    tile_s[(lc + 1) * TPITCH + lr] = v.y;
                }
            }
        }
    }

    if (!diag) {
        __syncthreads();
        // Mirror tile (tj, ti): coalesced float4 stores; conflict-free reads.
#pragma unroll
        for (int it = 0; it < 16; it++) {
            int e  = it * 256 + tid;           // 0..4095 float4 slots
            int c  = e >> 5;                   // 0..127
            int rq = e & 31;
            float4 w = *reinterpret_cast<float4*>(tile_s + c * TPITCH + rq * 4);
            int gr = tj * TILE + c;
            if (gr < M_OUT)
                *reinterpret_cast<float4*>(
                    outb + (long)gr * M + ti * TILE + rq * 4) = w;
        }
    }
}

// ---------------------------------------------------------------------------
extern "C" void kernel_launch(void* const* d_in, const int* in_sizes, int n_in,
                              void* d_out, int out_size) {
    const float* sp = (const float*)d_in[0];
    const float* tp = (const float*)d_in[1];
    if (n_in >= 2 && in_sizes[0] < in_sizes[1]) {
        sp = (const float*)d_in[1];
        tp = (const float*)d_in[0];
    }
    float* out = (float*)d_out;

    const int TOT = B_ * M_PAD * (KD / 4);
    convert_split_kernel<<<(TOT + 255) / 256, 256>>>(
        (const float4*)sp, (const float4*)tp);

    cudaFuncSetAttribute(gram_kernel,
                         cudaFuncAttributeMaxDynamicSharedMemorySize, SMEM_BYTES);
    dim3 grid(NPAIRS, B_);
    gram_kernel<<<grid, 256, SMEM_BYTES>>>(out);
}